// round 1
// baseline (speedup 1.0000x reference)
#include <cuda_runtime.h>
#include <math.h>

// Problem constants
#define D_MODEL 1024
#define SEQ     2048
#define BATCH   2
#define HEADS   16
#define HEAD_DIM 64
#define MTOT (BATCH * SEQ)   // 4096 rows

// Scratch (device globals: no allocation allowed)
__device__ float g_Q[MTOT * D_MODEL];
__device__ float g_K[MTOT * D_MODEL];
__device__ float g_V[MTOT * D_MODEL];
__device__ float g_O[MTOT * D_MODEL];

// ---------------------------------------------------------------------------
// SGEMM: C[4096,1024] = A[4096,1024] * W[1024,1024] + bias
// 128x128 block tile, K-tile 8, 256 threads, 8x8 per thread, float4 frags.
// ---------------------------------------------------------------------------
#define GBM 128
#define GBN 128
#define GBK 8

__global__ __launch_bounds__(256) void sgemm_bias_kernel(
    const float* __restrict__ A, const float* __restrict__ W,
    const float* __restrict__ bias, float* __restrict__ C)
{
    __shared__ float As[GBK][GBM];   // k-major (transposed at load)
    __shared__ float Bs[GBK][GBN];   // k-major (natural)

    const int tid = threadIdx.x;
    const int tx  = tid & 15;        // 0..15 -> col group
    const int ty  = tid >> 4;        // 0..15 -> row group
    const int rowBlk = blockIdx.y * GBM;
    const int colBlk = blockIdx.x * GBN;

    // load indices
    const int a_row = tid >> 1;          // 0..127
    const int a_col = (tid & 1) * 4;     // 0 or 4
    const int b_row = tid >> 5;          // 0..7
    const int b_col = (tid & 31) * 4;    // 0..124

    float acc[8][8];
#pragma unroll
    for (int i = 0; i < 8; i++)
#pragma unroll
        for (int j = 0; j < 8; j++) acc[i][j] = 0.0f;

    for (int k0 = 0; k0 < D_MODEL; k0 += GBK) {
        float4 av = *reinterpret_cast<const float4*>(
            &A[(size_t)(rowBlk + a_row) * D_MODEL + k0 + a_col]);
        As[a_col + 0][a_row] = av.x;
        As[a_col + 1][a_row] = av.y;
        As[a_col + 2][a_row] = av.z;
        As[a_col + 3][a_row] = av.w;
        *reinterpret_cast<float4*>(&Bs[b_row][b_col]) =
            *reinterpret_cast<const float4*>(
                &W[(size_t)(k0 + b_row) * D_MODEL + colBlk + b_col]);
        __syncthreads();

#pragma unroll
        for (int k = 0; k < GBK; k++) {
            float af[8], bf[8];
            *reinterpret_cast<float4*>(&af[0]) =
                *reinterpret_cast<float4*>(&As[k][ty * 8]);
            *reinterpret_cast<float4*>(&af[4]) =
                *reinterpret_cast<float4*>(&As[k][ty * 8 + 4]);
            *reinterpret_cast<float4*>(&bf[0]) =
                *reinterpret_cast<float4*>(&Bs[k][tx * 8]);
            *reinterpret_cast<float4*>(&bf[4]) =
                *reinterpret_cast<float4*>(&Bs[k][tx * 8 + 4]);
#pragma unroll
            for (int i = 0; i < 8; i++)
#pragma unroll
                for (int j = 0; j < 8; j++)
                    acc[i][j] = fmaf(af[i], bf[j], acc[i][j]);
        }
        __syncthreads();
    }

#pragma unroll
    for (int i = 0; i < 8; i++) {
        const int r = rowBlk + ty * 8 + i;
#pragma unroll
        for (int j = 0; j < 8; j += 4) {
            const int c = colBlk + tx * 8 + j;
            float4 o;
            o.x = acc[i][j + 0] + bias[c + 0];
            o.y = acc[i][j + 1] + bias[c + 1];
            o.z = acc[i][j + 2] + bias[c + 2];
            o.w = acc[i][j + 3] + bias[c + 3];
            *reinterpret_cast<float4*>(&C[(size_t)r * D_MODEL + c]) = o;
        }
    }
}

// ---------------------------------------------------------------------------
// Flash attention, fp32. One block = 64 query rows of one (b,h).
// 256 threads (16x16), 4x4 register tile per thread.
// smem: Qt[64][68] (d-major), KPt[64][68] (K d-major, reused as P k-major),
//       Vs[64][64] (natural). Online softmax stats in registers (replicated
//       across the 16 lanes that own a row group).
// ---------------------------------------------------------------------------
#define PADR 68   // 68*4 = 272B rows: 16B-aligned, breaks transpose conflicts

__global__ __launch_bounds__(256) void attn_kernel()
{
    extern __shared__ float sm[];
    float* Qt  = sm;                  // 64*PADR
    float* KPt = sm + 64 * PADR;      // 64*PADR
    float* Vs  = sm + 2 * 64 * PADR;  // 64*64

    const int tid = threadIdx.x;
    const int tx = tid & 15;
    const int ty = tid >> 4;
    const int qblk = blockIdx.x;            // 0..31
    const int bh   = blockIdx.y;            // 0..31
    const int b = bh >> 4;
    const int h = bh & 15;
    const size_t baseRow = (size_t)b * SEQ;
    const int colOff = h * HEAD_DIM;
    const float scale = 0.03125f;           // 1/sqrt(D_MODEL=1024)

    // Load Q tile, scaled, transposed to d-major
#pragma unroll
    for (int it = 0; it < 4; it++) {
        const int idx = tid + 256 * it;
        const int r  = idx >> 4;
        const int d4 = (idx & 15) << 2;
        float4 q = *reinterpret_cast<const float4*>(
            &g_Q[(baseRow + qblk * 64 + r) * D_MODEL + colOff + d4]);
        Qt[(d4 + 0) * PADR + r] = q.x * scale;
        Qt[(d4 + 1) * PADR + r] = q.y * scale;
        Qt[(d4 + 2) * PADR + r] = q.z * scale;
        Qt[(d4 + 3) * PADR + r] = q.w * scale;
    }

    float acc[4][4];
#pragma unroll
    for (int i = 0; i < 4; i++)
#pragma unroll
        for (int j = 0; j < 4; j++) acc[i][j] = 0.0f;
    float mrow[4], lrow[4];
#pragma unroll
    for (int i = 0; i < 4; i++) { mrow[i] = -INFINITY; lrow[i] = 0.0f; }

    for (int kt = 0; kt < SEQ / 64; kt++) {
        // Load K (transposed) and V (natural)
#pragma unroll
        for (int it = 0; it < 4; it++) {
            const int idx = tid + 256 * it;
            const int r  = idx >> 4;
            const int d4 = (idx & 15) << 2;
            const size_t g = (baseRow + kt * 64 + r) * D_MODEL + colOff + d4;
            float4 kv = *reinterpret_cast<const float4*>(&g_K[g]);
            KPt[(d4 + 0) * PADR + r] = kv.x;
            KPt[(d4 + 1) * PADR + r] = kv.y;
            KPt[(d4 + 2) * PADR + r] = kv.z;
            KPt[(d4 + 3) * PADR + r] = kv.w;
            *reinterpret_cast<float4*>(&Vs[r * 64 + d4]) =
                *reinterpret_cast<const float4*>(&g_V[g]);
        }
        __syncthreads();

        // S = (Q*scale) @ K^T   (4x4 per thread)
        float s[4][4];
#pragma unroll
        for (int i = 0; i < 4; i++)
#pragma unroll
            for (int j = 0; j < 4; j++) s[i][j] = 0.0f;
#pragma unroll 8
        for (int d = 0; d < 64; d++) {
            float4 a  = *reinterpret_cast<float4*>(&Qt[d * PADR + ty * 4]);
            float4 bb = *reinterpret_cast<float4*>(&KPt[d * PADR + tx * 4]);
            const float af[4] = {a.x, a.y, a.z, a.w};
            const float bf[4] = {bb.x, bb.y, bb.z, bb.w};
#pragma unroll
            for (int i = 0; i < 4; i++)
#pragma unroll
                for (int j = 0; j < 4; j++)
                    s[i][j] = fmaf(af[i], bf[j], s[i][j]);
        }
        __syncthreads();   // all reads of KPt done before P overwrites it

        // Online softmax (rows owned by the 16 lanes sharing ty)
#pragma unroll
        for (int i = 0; i < 4; i++) {
            float lm = fmaxf(fmaxf(s[i][0], s[i][1]), fmaxf(s[i][2], s[i][3]));
            lm = fmaxf(lm, __shfl_xor_sync(0xffffffffu, lm, 1));
            lm = fmaxf(lm, __shfl_xor_sync(0xffffffffu, lm, 2));
            lm = fmaxf(lm, __shfl_xor_sync(0xffffffffu, lm, 4));
            lm = fmaxf(lm, __shfl_xor_sync(0xffffffffu, lm, 8));
            const float mnew  = fmaxf(mrow[i], lm);
            const float alpha = __expf(mrow[i] - mnew);
            mrow[i] = mnew;
            float rs = 0.0f;
#pragma unroll
            for (int j = 0; j < 4; j++) {
                s[i][j] = __expf(s[i][j] - mnew);
                rs += s[i][j];
            }
            rs += __shfl_xor_sync(0xffffffffu, rs, 1);
            rs += __shfl_xor_sync(0xffffffffu, rs, 2);
            rs += __shfl_xor_sync(0xffffffffu, rs, 4);
            rs += __shfl_xor_sync(0xffffffffu, rs, 8);
            lrow[i] = lrow[i] * alpha + rs;
#pragma unroll
            for (int j = 0; j < 4; j++) acc[i][j] *= alpha;
            // write P transposed (k-major) into KPt
#pragma unroll
            for (int j = 0; j < 4; j++)
                KPt[(tx * 4 + j) * PADR + ty * 4 + i] = s[i][j];
        }
        __syncthreads();

        // O += P @ V
#pragma unroll 8
        for (int k = 0; k < 64; k++) {
            float4 a  = *reinterpret_cast<float4*>(&KPt[k * PADR + ty * 4]);
            float4 bb = *reinterpret_cast<float4*>(&Vs[k * 64 + tx * 4]);
            const float af[4] = {a.x, a.y, a.z, a.w};
            const float bf[4] = {bb.x, bb.y, bb.z, bb.w};
#pragma unroll
            for (int i = 0; i < 4; i++)
#pragma unroll
                for (int j = 0; j < 4; j++)
                    acc[i][j] = fmaf(af[i], bf[j], acc[i][j]);
        }
        __syncthreads();   // before next tile overwrites KPt/Vs
    }

    // Normalize and store merged-head output
#pragma unroll
    for (int i = 0; i < 4; i++) {
        const float rinv = 1.0f / lrow[i];
        float4 o;
        o.x = acc[i][0] * rinv;
        o.y = acc[i][1] * rinv;
        o.z = acc[i][2] * rinv;
        o.w = acc[i][3] * rinv;
        *reinterpret_cast<float4*>(
            &g_O[(baseRow + qblk * 64 + ty * 4 + i) * D_MODEL + colOff + tx * 4]) = o;
    }
}

// ---------------------------------------------------------------------------
extern "C" void kernel_launch(void* const* d_in, const int* in_sizes, int n_in,
                              void* d_out, int out_size)
{
    const float* queries = (const float*)d_in[0];
    const float* keys    = (const float*)d_in[1];
    const float* values  = (const float*)d_in[2];
    const float* Wq = (const float*)d_in[3];
    const float* bq = (const float*)d_in[4];
    const float* Wk = (const float*)d_in[5];
    const float* bk = (const float*)d_in[6];
    const float* Wv = (const float*)d_in[7];
    const float* bv = (const float*)d_in[8];
    const float* Wo = (const float*)d_in[9];
    const float* bo = (const float*)d_in[10];
    float* out = (float*)d_out;

    float *Qp, *Kp, *Vp, *Op;
    cudaGetSymbolAddress((void**)&Qp, g_Q);
    cudaGetSymbolAddress((void**)&Kp, g_K);
    cudaGetSymbolAddress((void**)&Vp, g_V);
    cudaGetSymbolAddress((void**)&Op, g_O);

    const dim3 gemmGrid(D_MODEL / GBN, MTOT / GBM);   // (8, 32)

    sgemm_bias_kernel<<<gemmGrid, 256>>>(queries, Wq, bq, Qp);
    sgemm_bias_kernel<<<gemmGrid, 256>>>(keys,    Wk, bk, Kp);
    sgemm_bias_kernel<<<gemmGrid, 256>>>(values,  Wv, bv, Vp);

    const int attnSmem = (2 * 64 * PADR + 64 * 64) * (int)sizeof(float); // 51200B
    cudaFuncSetAttribute(attn_kernel,
                         cudaFuncAttributeMaxDynamicSharedMemorySize, attnSmem);
    attn_kernel<<<dim3(SEQ / 64, BATCH * HEADS), 256, attnSmem>>>();

    sgemm_bias_kernel<<<gemmGrid, 256>>>(Op, Wo, bo, out);
}

// round 2
// speedup vs baseline: 1.3856x; 1.3856x over previous
#include <cuda_runtime.h>
#include <math.h>
#include <stdint.h>

// Problem constants
#define D_MODEL 1024
#define SEQ     2048
#define BATCH   2
#define HEADS   16
#define HEAD_DIM 64
#define MTOT (BATCH * SEQ)   // 4096 rows

// Scratch (device globals: no allocation allowed)
__device__ float g_Q[MTOT * D_MODEL];
__device__ float g_K[MTOT * D_MODEL];
__device__ float g_V[MTOT * D_MODEL];
__device__ float g_O[MTOT * D_MODEL];

// ---------------------------------------------------------------------------
// tf32 tensor-core GEMM: C[4096,1024] = A[4096,1024] * W[1024,1024] + bias
// 128x128 block tile, BK=16, 256 threads (8 warps, 64x32 warp tile),
// m16n8k8 tf32 mma, double-buffered smem.
// A smem: m-major [128][20]  (stride 20 -> conflict-free frag gather + STS.128)
// B smem: k-major [16][136]  (stride 136 -> conflict-free frag gather)
// ---------------------------------------------------------------------------
#define BM 128
#define BN 128
#define BK 16
#define SA_STRIDE 20
#define SB_STRIDE 136

__device__ __forceinline__ uint32_t f2tf32(float x) {
    uint32_t u;
    asm("cvt.rna.tf32.f32 %0, %1;" : "=r"(u) : "f"(x));
    return u;
}

__device__ __forceinline__ void mma_tf32(
    float& d0, float& d1, float& d2, float& d3,
    uint32_t a0, uint32_t a1, uint32_t a2, uint32_t a3,
    uint32_t b0, uint32_t b1)
{
    asm volatile(
        "mma.sync.aligned.m16n8k8.row.col.f32.tf32.tf32.f32 "
        "{%0,%1,%2,%3}, {%4,%5,%6,%7}, {%8,%9}, {%0,%1,%2,%3};\n"
        : "+f"(d0), "+f"(d1), "+f"(d2), "+f"(d3)
        : "r"(a0), "r"(a1), "r"(a2), "r"(a3), "r"(b0), "r"(b1));
}

__global__ __launch_bounds__(256) void gemm_tf32_kernel(
    const float* __restrict__ A, const float* __restrict__ W,
    const float* __restrict__ bias, float* __restrict__ C)
{
    __shared__ uint32_t As[2][BM][SA_STRIDE];   // 2*128*20*4  = 20480 B
    __shared__ uint32_t Bs[2][BK][SB_STRIDE];   // 2*16*136*4  = 17408 B

    const int tid  = threadIdx.x;
    const int warp = tid >> 5;
    const int lane = tid & 31;
    const int wm = (warp & 1) * 64;          // warp row offset
    const int wn = (warp >> 1) * 32;         // warp col offset
    const int rowBlk = blockIdx.y * BM;
    const int colBlk = blockIdx.x * BN;

    const int lr = lane >> 2;   // 0..7
    const int lc = lane & 3;    // 0..3

    // global-load indices (each thread: 2 float4 of A, 2 float4 of B)
    const int a_r  = tid >> 1;           // 0..127  (idx = tid+256i -> r=idx>>2? use 2/thread layout)
    // A: 128x16 = 512 float4; idx = tid + 256*i; r = idx>>2, c4 = (idx&3)<<2
    // B: 16x128 = 512 float4; k = idx>>5, n4 = (idx&31)<<2
    (void)a_r;

    float acc[4][4][4];
#pragma unroll
    for (int mi = 0; mi < 4; mi++)
#pragma unroll
        for (int ni = 0; ni < 4; ni++)
#pragma unroll
            for (int r = 0; r < 4; r++) acc[mi][ni][r] = 0.0f;

    auto load_tile = [&](int t, int buf) {
#pragma unroll
        for (int i = 0; i < 2; i++) {
            const int idx = tid + 256 * i;
            const int r  = idx >> 2;
            const int c4 = (idx & 3) << 2;
            float4 v = *reinterpret_cast<const float4*>(
                &A[(size_t)(rowBlk + r) * D_MODEL + t * BK + c4]);
            uint4 u;
            u.x = f2tf32(v.x); u.y = f2tf32(v.y);
            u.z = f2tf32(v.z); u.w = f2tf32(v.w);
            *reinterpret_cast<uint4*>(&As[buf][r][c4]) = u;
        }
#pragma unroll
        for (int i = 0; i < 2; i++) {
            const int idx = tid + 256 * i;
            const int k  = idx >> 5;
            const int n4 = (idx & 31) << 2;
            float4 v = *reinterpret_cast<const float4*>(
                &W[(size_t)(t * BK + k) * D_MODEL + colBlk + n4]);
            uint4 u;
            u.x = f2tf32(v.x); u.y = f2tf32(v.y);
            u.z = f2tf32(v.z); u.w = f2tf32(v.w);
            *reinterpret_cast<uint4*>(&Bs[buf][k][n4]) = u;
        }
    };

    load_tile(0, 0);
    __syncthreads();

    const int NT = D_MODEL / BK;   // 64
    for (int t = 0; t < NT; t++) {
        const int buf = t & 1;
        if (t + 1 < NT) load_tile(t + 1, (t + 1) & 1);

#pragma unroll
        for (int s = 0; s < 2; s++) {
            const int k0 = s * 8;
            uint32_t af[4][4];
#pragma unroll
            for (int mi = 0; mi < 4; mi++) {
                const int m = wm + mi * 16 + lr;
                af[mi][0] = As[buf][m    ][k0 + lc];
                af[mi][1] = As[buf][m + 8][k0 + lc];
                af[mi][2] = As[buf][m    ][k0 + lc + 4];
                af[mi][3] = As[buf][m + 8][k0 + lc + 4];
            }
            uint32_t bf[4][2];
#pragma unroll
            for (int ni = 0; ni < 4; ni++) {
                const int n = wn + ni * 8 + lr;
                bf[ni][0] = Bs[buf][k0 + lc    ][n];
                bf[ni][1] = Bs[buf][k0 + lc + 4][n];
            }
#pragma unroll
            for (int mi = 0; mi < 4; mi++)
#pragma unroll
                for (int ni = 0; ni < 4; ni++)
                    mma_tf32(acc[mi][ni][0], acc[mi][ni][1],
                             acc[mi][ni][2], acc[mi][ni][3],
                             af[mi][0], af[mi][1], af[mi][2], af[mi][3],
                             bf[ni][0], bf[ni][1]);
        }
        __syncthreads();
    }

    // epilogue: bias add + store (c0,c1 at (r, 2c), c2,c3 at (r+8, 2c))
#pragma unroll
    for (int mi = 0; mi < 4; mi++) {
        const int row0 = rowBlk + wm + mi * 16 + lr;
#pragma unroll
        for (int ni = 0; ni < 4; ni++) {
            const int col = colBlk + wn + ni * 8 + lc * 2;
            const float2 bb = *reinterpret_cast<const float2*>(&bias[col]);
            float2 o0, o1;
            o0.x = acc[mi][ni][0] + bb.x;
            o0.y = acc[mi][ni][1] + bb.y;
            o1.x = acc[mi][ni][2] + bb.x;
            o1.y = acc[mi][ni][3] + bb.y;
            *reinterpret_cast<float2*>(&C[(size_t)row0 * D_MODEL + col]) = o0;
            *reinterpret_cast<float2*>(&C[(size_t)(row0 + 8) * D_MODEL + col]) = o1;
        }
    }
}

// ---------------------------------------------------------------------------
// Flash attention, fp32 (unchanged from R1 passing version).
// ---------------------------------------------------------------------------
#define PADR 68

__global__ __launch_bounds__(256) void attn_kernel()
{
    extern __shared__ float sm[];
    float* Qt  = sm;                  // 64*PADR
    float* KPt = sm + 64 * PADR;      // 64*PADR
    float* Vs  = sm + 2 * 64 * PADR;  // 64*64

    const int tid = threadIdx.x;
    const int tx = tid & 15;
    const int ty = tid >> 4;
    const int qblk = blockIdx.x;
    const int bh   = blockIdx.y;
    const int b = bh >> 4;
    const int h = bh & 15;
    const size_t baseRow = (size_t)b * SEQ;
    const int colOff = h * HEAD_DIM;
    const float scale = 0.03125f;     // 1/sqrt(1024)

#pragma unroll
    for (int it = 0; it < 4; it++) {
        const int idx = tid + 256 * it;
        const int r  = idx >> 4;
        const int d4 = (idx & 15) << 2;
        float4 q = *reinterpret_cast<const float4*>(
            &g_Q[(baseRow + qblk * 64 + r) * D_MODEL + colOff + d4]);
        Qt[(d4 + 0) * PADR + r] = q.x * scale;
        Qt[(d4 + 1) * PADR + r] = q.y * scale;
        Qt[(d4 + 2) * PADR + r] = q.z * scale;
        Qt[(d4 + 3) * PADR + r] = q.w * scale;
    }

    float acc[4][4];
#pragma unroll
    for (int i = 0; i < 4; i++)
#pragma unroll
        for (int j = 0; j < 4; j++) acc[i][j] = 0.0f;
    float mrow[4], lrow[4];
#pragma unroll
    for (int i = 0; i < 4; i++) { mrow[i] = -INFINITY; lrow[i] = 0.0f; }

    for (int kt = 0; kt < SEQ / 64; kt++) {
#pragma unroll
        for (int it = 0; it < 4; it++) {
            const int idx = tid + 256 * it;
            const int r  = idx >> 4;
            const int d4 = (idx & 15) << 2;
            const size_t g = (baseRow + kt * 64 + r) * D_MODEL + colOff + d4;
            float4 kv = *reinterpret_cast<const float4*>(&g_K[g]);
            KPt[(d4 + 0) * PADR + r] = kv.x;
            KPt[(d4 + 1) * PADR + r] = kv.y;
            KPt[(d4 + 2) * PADR + r] = kv.z;
            KPt[(d4 + 3) * PADR + r] = kv.w;
            *reinterpret_cast<float4*>(&Vs[r * 64 + d4]) =
                *reinterpret_cast<const float4*>(&g_V[g]);
        }
        __syncthreads();

        float s[4][4];
#pragma unroll
        for (int i = 0; i < 4; i++)
#pragma unroll
            for (int j = 0; j < 4; j++) s[i][j] = 0.0f;
#pragma unroll 8
        for (int d = 0; d < 64; d++) {
            float4 a  = *reinterpret_cast<float4*>(&Qt[d * PADR + ty * 4]);
            float4 bb = *reinterpret_cast<float4*>(&KPt[d * PADR + tx * 4]);
            const float af[4] = {a.x, a.y, a.z, a.w};
            const float bf[4] = {bb.x, bb.y, bb.z, bb.w};
#pragma unroll
            for (int i = 0; i < 4; i++)
#pragma unroll
                for (int j = 0; j < 4; j++)
                    s[i][j] = fmaf(af[i], bf[j], s[i][j]);
        }
        __syncthreads();

#pragma unroll
        for (int i = 0; i < 4; i++) {
            float lm = fmaxf(fmaxf(s[i][0], s[i][1]), fmaxf(s[i][2], s[i][3]));
            lm = fmaxf(lm, __shfl_xor_sync(0xffffffffu, lm, 1));
            lm = fmaxf(lm, __shfl_xor_sync(0xffffffffu, lm, 2));
            lm = fmaxf(lm, __shfl_xor_sync(0xffffffffu, lm, 4));
            lm = fmaxf(lm, __shfl_xor_sync(0xffffffffu, lm, 8));
            const float mnew  = fmaxf(mrow[i], lm);
            const float alpha = __expf(mrow[i] - mnew);
            mrow[i] = mnew;
            float rs = 0.0f;
#pragma unroll
            for (int j = 0; j < 4; j++) {
                s[i][j] = __expf(s[i][j] - mnew);
                rs += s[i][j];
            }
            rs += __shfl_xor_sync(0xffffffffu, rs, 1);
            rs += __shfl_xor_sync(0xffffffffu, rs, 2);
            rs += __shfl_xor_sync(0xffffffffu, rs, 4);
            rs += __shfl_xor_sync(0xffffffffu, rs, 8);
            lrow[i] = lrow[i] * alpha + rs;
#pragma unroll
            for (int j = 0; j < 4; j++) acc[i][j] *= alpha;
#pragma unroll
            for (int j = 0; j < 4; j++)
                KPt[(tx * 4 + j) * PADR + ty * 4 + i] = s[i][j];
        }
        __syncthreads();

#pragma unroll 8
        for (int k = 0; k < 64; k++) {
            float4 a  = *reinterpret_cast<float4*>(&KPt[k * PADR + ty * 4]);
            float4 bb = *reinterpret_cast<float4*>(&Vs[k * 64 + tx * 4]);
            const float af[4] = {a.x, a.y, a.z, a.w};
            const float bf[4] = {bb.x, bb.y, bb.z, bb.w};
#pragma unroll
            for (int i = 0; i < 4; i++)
#pragma unroll
                for (int j = 0; j < 4; j++)
                    acc[i][j] = fmaf(af[i], bf[j], acc[i][j]);
        }
        __syncthreads();
    }

#pragma unroll
    for (int i = 0; i < 4; i++) {
        const float rinv = 1.0f / lrow[i];
        float4 o;
        o.x = acc[i][0] * rinv;
        o.y = acc[i][1] * rinv;
        o.z = acc[i][2] * rinv;
        o.w = acc[i][3] * rinv;
        *reinterpret_cast<float4*>(
            &g_O[(baseRow + qblk * 64 + ty * 4 + i) * D_MODEL + colOff + tx * 4]) = o;
    }
}

// ---------------------------------------------------------------------------
extern "C" void kernel_launch(void* const* d_in, const int* in_sizes, int n_in,
                              void* d_out, int out_size)
{
    const float* queries = (const float*)d_in[0];
    const float* keys    = (const float*)d_in[1];
    const float* values  = (const float*)d_in[2];
    const float* Wq = (const float*)d_in[3];
    const float* bq = (const float*)d_in[4];
    const float* Wk = (const float*)d_in[5];
    const float* bk = (const float*)d_in[6];
    const float* Wv = (const float*)d_in[7];
    const float* bv = (const float*)d_in[8];
    const float* Wo = (const float*)d_in[9];
    const float* bo = (const float*)d_in[10];
    float* out = (float*)d_out;

    float *Qp, *Kp, *Vp, *Op;
    cudaGetSymbolAddress((void**)&Qp, g_Q);
    cudaGetSymbolAddress((void**)&Kp, g_K);
    cudaGetSymbolAddress((void**)&Vp, g_V);
    cudaGetSymbolAddress((void**)&Op, g_O);

    const dim3 gemmGrid(D_MODEL / BN, MTOT / BM);   // (8, 32)

    gemm_tf32_kernel<<<gemmGrid, 256>>>(queries, Wq, bq, Qp);
    gemm_tf32_kernel<<<gemmGrid, 256>>>(keys,    Wk, bk, Kp);
    gemm_tf32_kernel<<<gemmGrid, 256>>>(values,  Wv, bv, Vp);

    const int attnSmem = (2 * 64 * PADR + 64 * 64) * (int)sizeof(float); // 51200B
    cudaFuncSetAttribute(attn_kernel,
                         cudaFuncAttributeMaxDynamicSharedMemorySize, attnSmem);
    attn_kernel<<<dim3(SEQ / 64, BATCH * HEADS), 256, attnSmem>>>();

    gemm_tf32_kernel<<<gemmGrid, 256>>>(Op, Wo, bo, out);
}

// round 3
// speedup vs baseline: 2.6220x; 1.8923x over previous
#include <cuda_runtime.h>
#include <math.h>
#include <stdint.h>

// Problem constants
#define D_MODEL 1024
#define SEQ     2048
#define BATCH   2
#define HEADS   16
#define HEAD_DIM 64
#define MTOT (BATCH * SEQ)   // 4096 rows

// Scratch (device globals: no allocation allowed)
__device__ float g_Q[MTOT * D_MODEL];
__device__ float g_K[MTOT * D_MODEL];
__device__ float g_V[MTOT * D_MODEL];
__device__ float g_O[MTOT * D_MODEL];

__device__ __forceinline__ uint32_t f2tf32(float x) {
    uint32_t u;
    asm("cvt.rna.tf32.f32 %0, %1;" : "=r"(u) : "f"(x));
    return u;
}

__device__ __forceinline__ void mma_tf32(
    float& d0, float& d1, float& d2, float& d3,
    uint32_t a0, uint32_t a1, uint32_t a2, uint32_t a3,
    uint32_t b0, uint32_t b1)
{
    asm volatile(
        "mma.sync.aligned.m16n8k8.row.col.f32.tf32.tf32.f32 "
        "{%0,%1,%2,%3}, {%4,%5,%6,%7}, {%8,%9}, {%0,%1,%2,%3};\n"
        : "+f"(d0), "+f"(d1), "+f"(d2), "+f"(d3)
        : "r"(a0), "r"(a1), "r"(a2), "r"(a3), "r"(b0), "r"(b1));
}

// ---------------------------------------------------------------------------
// tf32 tensor-core GEMM (unchanged from R2, proven 4x faster than SIMT).
// ---------------------------------------------------------------------------
#define BM 128
#define BN 128
#define BK 16
#define SA_STRIDE 20
#define SB_STRIDE 136

__global__ __launch_bounds__(256) void gemm_tf32_kernel(
    const float* __restrict__ A, const float* __restrict__ W,
    const float* __restrict__ bias, float* __restrict__ C)
{
    __shared__ uint32_t As[2][BM][SA_STRIDE];
    __shared__ uint32_t Bs[2][BK][SB_STRIDE];

    const int tid  = threadIdx.x;
    const int warp = tid >> 5;
    const int lane = tid & 31;
    const int wm = (warp & 1) * 64;
    const int wn = (warp >> 1) * 32;
    const int rowBlk = blockIdx.y * BM;
    const int colBlk = blockIdx.x * BN;
    const int lr = lane >> 2;
    const int lc = lane & 3;

    float acc[4][4][4];
#pragma unroll
    for (int mi = 0; mi < 4; mi++)
#pragma unroll
        for (int ni = 0; ni < 4; ni++)
#pragma unroll
            for (int r = 0; r < 4; r++) acc[mi][ni][r] = 0.0f;

    auto load_tile = [&](int t, int buf) {
#pragma unroll
        for (int i = 0; i < 2; i++) {
            const int idx = tid + 256 * i;
            const int r  = idx >> 2;
            const int c4 = (idx & 3) << 2;
            float4 v = *reinterpret_cast<const float4*>(
                &A[(size_t)(rowBlk + r) * D_MODEL + t * BK + c4]);
            uint4 u;
            u.x = f2tf32(v.x); u.y = f2tf32(v.y);
            u.z = f2tf32(v.z); u.w = f2tf32(v.w);
            *reinterpret_cast<uint4*>(&As[buf][r][c4]) = u;
        }
#pragma unroll
        for (int i = 0; i < 2; i++) {
            const int idx = tid + 256 * i;
            const int k  = idx >> 5;
            const int n4 = (idx & 31) << 2;
            float4 v = *reinterpret_cast<const float4*>(
                &W[(size_t)(t * BK + k) * D_MODEL + colBlk + n4]);
            uint4 u;
            u.x = f2tf32(v.x); u.y = f2tf32(v.y);
            u.z = f2tf32(v.z); u.w = f2tf32(v.w);
            *reinterpret_cast<uint4*>(&Bs[buf][k][n4]) = u;
        }
    };

    load_tile(0, 0);
    __syncthreads();

    const int NT = D_MODEL / BK;
    for (int t = 0; t < NT; t++) {
        const int buf = t & 1;
        if (t + 1 < NT) load_tile(t + 1, (t + 1) & 1);

#pragma unroll
        for (int s = 0; s < 2; s++) {
            const int k0 = s * 8;
            uint32_t af[4][4];
#pragma unroll
            for (int mi = 0; mi < 4; mi++) {
                const int m = wm + mi * 16 + lr;
                af[mi][0] = As[buf][m    ][k0 + lc];
                af[mi][1] = As[buf][m + 8][k0 + lc];
                af[mi][2] = As[buf][m    ][k0 + lc + 4];
                af[mi][3] = As[buf][m + 8][k0 + lc + 4];
            }
            uint32_t bf[4][2];
#pragma unroll
            for (int ni = 0; ni < 4; ni++) {
                const int n = wn + ni * 8 + lr;
                bf[ni][0] = Bs[buf][k0 + lc    ][n];
                bf[ni][1] = Bs[buf][k0 + lc + 4][n];
            }
#pragma unroll
            for (int mi = 0; mi < 4; mi++)
#pragma unroll
                for (int ni = 0; ni < 4; ni++)
                    mma_tf32(acc[mi][ni][0], acc[mi][ni][1],
                             acc[mi][ni][2], acc[mi][ni][3],
                             af[mi][0], af[mi][1], af[mi][2], af[mi][3],
                             bf[ni][0], bf[ni][1]);
        }
        __syncthreads();
    }

#pragma unroll
    for (int mi = 0; mi < 4; mi++) {
        const int row0 = rowBlk + wm + mi * 16 + lr;
#pragma unroll
        for (int ni = 0; ni < 4; ni++) {
            const int col = colBlk + wn + ni * 8 + lc * 2;
            const float2 bb = *reinterpret_cast<const float2*>(&bias[col]);
            float2 o0, o1;
            o0.x = acc[mi][ni][0] + bb.x;
            o0.y = acc[mi][ni][1] + bb.y;
            o1.x = acc[mi][ni][2] + bb.x;
            o1.y = acc[mi][ni][3] + bb.y;
            *reinterpret_cast<float2*>(&C[(size_t)row0 * D_MODEL + col]) = o0;
            *reinterpret_cast<float2*>(&C[(size_t)(row0 + 8) * D_MODEL + col]) = o1;
        }
    }
}

// ---------------------------------------------------------------------------
// tf32 tensor-core flash attention.
// Block = 128 query rows of one (b,h); 8 warps, each owns 16 rows x 64 cols.
// Q kept in registers as tf32 A-frags. K smem [key][d] stride 68 (conflict-
// free B gather: bank 4*lr+lc). V smem [key][d] stride 72 (bank 8*lc+lr).
// P round-trips through smem stride 68 as tf32. Softmax warp-local on the
// mma accumulator layout.
// ---------------------------------------------------------------------------
#define QTILE 128
#define KCH 64            // keys per chunk
#define KST 68            // K / P smem stride (== 4 mod 32)
#define VST 72            // V smem stride (== 8 mod 32)
#define ASM_K (64 * KST)                // Ksm words
#define ASM_V (64 * VST)                // Vsm words
#define ASM_P (QTILE * KST)             // Psm words
#define ATTN_SMEM ((ASM_K + ASM_V + ASM_P) * 4)   // 70656 bytes

__global__ __launch_bounds__(256) void attn_kernel()
{
    extern __shared__ uint32_t smu[];
    uint32_t* Ksm = smu;                     // [64][KST] tf32
    uint32_t* Vsm = smu + ASM_K;             // [64][VST] tf32
    uint32_t* Psm = smu + ASM_K + ASM_V;     // [128][KST] tf32 (Q staging first)

    const int tid  = threadIdx.x;
    const int warp = tid >> 5;
    const int lane = tid & 31;
    const int lr = lane >> 2;      // 0..7
    const int lc = lane & 3;       // 0..3
    const int wm = warp * 16;      // warp's row offset in the 128-row tile

    const int qblk = blockIdx.x;             // 0..15
    const int bh   = blockIdx.y;             // 0..31
    const int b = bh >> 4;
    const int h = bh & 15;
    const size_t baseRow = (size_t)b * SEQ;
    const int colOff = h * HEAD_DIM;
    const float scale = 0.03125f;            // 1/sqrt(1024)

    // ---- stage Q tile (scaled, tf32) into Psm, then lift to register frags
#pragma unroll
    for (int i = 0; i < 8; i++) {
        const int idx = tid + 256 * i;
        const int r  = idx >> 4;             // 0..127
        const int d4 = (idx & 15) << 2;
        float4 q = *reinterpret_cast<const float4*>(
            &g_Q[(baseRow + qblk * QTILE + r) * D_MODEL + colOff + d4]);
        uint4 u;
        u.x = f2tf32(q.x * scale); u.y = f2tf32(q.y * scale);
        u.z = f2tf32(q.z * scale); u.w = f2tf32(q.w * scale);
        *reinterpret_cast<uint4*>(&Psm[r * KST + d4]) = u;
    }
    __syncthreads();

    uint32_t qf[8][4];
#pragma unroll
    for (int ks = 0; ks < 8; ks++) {
        const int k0 = ks * 8;
        qf[ks][0] = Psm[(wm + lr    ) * KST + k0 + lc    ];
        qf[ks][1] = Psm[(wm + lr + 8) * KST + k0 + lc    ];
        qf[ks][2] = Psm[(wm + lr    ) * KST + k0 + lc + 4];
        qf[ks][3] = Psm[(wm + lr + 8) * KST + k0 + lc + 4];
    }
    // NOTE: iteration-0 __syncthreads below orders these reads before any P store.

    float oacc[8][4];
#pragma unroll
    for (int ni = 0; ni < 8; ni++)
#pragma unroll
        for (int r = 0; r < 4; r++) oacc[ni][r] = 0.0f;
    float m0 = -INFINITY, m1 = -INFINITY, l0 = 0.0f, l1 = 0.0f;

    for (int kt = 0; kt < SEQ / KCH; kt++) {
        // ---- load K and V chunks (tf32) ----
#pragma unroll
        for (int i = 0; i < 4; i++) {
            const int idx = tid + 256 * i;
            const int r  = idx >> 4;         // 0..63
            const int d4 = (idx & 15) << 2;
            const size_t g = (baseRow + kt * KCH + r) * D_MODEL + colOff + d4;
            float4 kv = *reinterpret_cast<const float4*>(&g_K[g]);
            uint4 uk;
            uk.x = f2tf32(kv.x); uk.y = f2tf32(kv.y);
            uk.z = f2tf32(kv.z); uk.w = f2tf32(kv.w);
            *reinterpret_cast<uint4*>(&Ksm[r * KST + d4]) = uk;
            float4 vv = *reinterpret_cast<const float4*>(&g_V[g]);
            uint4 uv;
            uv.x = f2tf32(vv.x); uv.y = f2tf32(vv.y);
            uv.z = f2tf32(vv.z); uv.w = f2tf32(vv.w);
            *reinterpret_cast<uint4*>(&Vsm[r * VST + d4]) = uv;
        }
        __syncthreads();

        // ---- S = Q @ K^T  (rows wm+lr / +8, cols ni*8 + 2lc,+1) ----
        float sacc[8][4];
#pragma unroll
        for (int ni = 0; ni < 8; ni++)
#pragma unroll
            for (int r = 0; r < 4; r++) sacc[ni][r] = 0.0f;
#pragma unroll
        for (int ks = 0; ks < 8; ks++) {
            const int k0 = ks * 8;
#pragma unroll
            for (int ni = 0; ni < 8; ni++) {
                const uint32_t b0 = Ksm[(ni * 8 + lr) * KST + k0 + lc    ];
                const uint32_t b1 = Ksm[(ni * 8 + lr) * KST + k0 + lc + 4];
                mma_tf32(sacc[ni][0], sacc[ni][1], sacc[ni][2], sacc[ni][3],
                         qf[ks][0], qf[ks][1], qf[ks][2], qf[ks][3], b0, b1);
            }
        }

        // ---- online softmax (warp-local; 4 lanes per row via xor 1,2) ----
        float lm0 = -INFINITY, lm1 = -INFINITY;
#pragma unroll
        for (int ni = 0; ni < 8; ni++) {
            lm0 = fmaxf(lm0, fmaxf(sacc[ni][0], sacc[ni][1]));
            lm1 = fmaxf(lm1, fmaxf(sacc[ni][2], sacc[ni][3]));
        }
        lm0 = fmaxf(lm0, __shfl_xor_sync(0xffffffffu, lm0, 1));
        lm0 = fmaxf(lm0, __shfl_xor_sync(0xffffffffu, lm0, 2));
        lm1 = fmaxf(lm1, __shfl_xor_sync(0xffffffffu, lm1, 1));
        lm1 = fmaxf(lm1, __shfl_xor_sync(0xffffffffu, lm1, 2));
        const float mn0 = fmaxf(m0, lm0);
        const float mn1 = fmaxf(m1, lm1);
        const float a0 = __expf(m0 - mn0);
        const float a1 = __expf(m1 - mn1);
        m0 = mn0; m1 = mn1;
        float rs0 = 0.0f, rs1 = 0.0f;
#pragma unroll
        for (int ni = 0; ni < 8; ni++) {
            sacc[ni][0] = __expf(sacc[ni][0] - mn0);
            sacc[ni][1] = __expf(sacc[ni][1] - mn0);
            sacc[ni][2] = __expf(sacc[ni][2] - mn1);
            sacc[ni][3] = __expf(sacc[ni][3] - mn1);
            rs0 += sacc[ni][0] + sacc[ni][1];
            rs1 += sacc[ni][2] + sacc[ni][3];
        }
        rs0 += __shfl_xor_sync(0xffffffffu, rs0, 1);
        rs0 += __shfl_xor_sync(0xffffffffu, rs0, 2);
        rs1 += __shfl_xor_sync(0xffffffffu, rs1, 1);
        rs1 += __shfl_xor_sync(0xffffffffu, rs1, 2);
        l0 = l0 * a0 + rs0;
        l1 = l1 * a1 + rs1;
#pragma unroll
        for (int ni = 0; ni < 8; ni++) {
            oacc[ni][0] *= a0; oacc[ni][1] *= a0;
            oacc[ni][2] *= a1; oacc[ni][3] *= a1;
        }

        // ---- write P (tf32) to smem for the O-mma A operand ----
#pragma unroll
        for (int ni = 0; ni < 8; ni++) {
            const int col = ni * 8 + lc * 2;
            uint2 p0, p1;
            p0.x = f2tf32(sacc[ni][0]); p0.y = f2tf32(sacc[ni][1]);
            p1.x = f2tf32(sacc[ni][2]); p1.y = f2tf32(sacc[ni][3]);
            *reinterpret_cast<uint2*>(&Psm[(wm + lr    ) * KST + col]) = p0;
            *reinterpret_cast<uint2*>(&Psm[(wm + lr + 8) * KST + col]) = p1;
        }
        __syncwarp();   // P rows are warp-private; warp-level visibility suffices

        // ---- O += P @ V ----
#pragma unroll
        for (int ks = 0; ks < 8; ks++) {
            const int k0 = ks * 8;
            uint32_t af0 = Psm[(wm + lr    ) * KST + k0 + lc    ];
            uint32_t af1 = Psm[(wm + lr + 8) * KST + k0 + lc    ];
            uint32_t af2 = Psm[(wm + lr    ) * KST + k0 + lc + 4];
            uint32_t af3 = Psm[(wm + lr + 8) * KST + k0 + lc + 4];
#pragma unroll
            for (int ni = 0; ni < 8; ni++) {
                const uint32_t b0 = Vsm[(k0 + lc    ) * VST + ni * 8 + lr];
                const uint32_t b1 = Vsm[(k0 + lc + 4) * VST + ni * 8 + lr];
                mma_tf32(oacc[ni][0], oacc[ni][1], oacc[ni][2], oacc[ni][3],
                         af0, af1, af2, af3, b0, b1);
            }
        }
        __syncthreads();   // K/V consumed; safe to overwrite next iteration
    }

    // ---- normalize and store ----
    const float inv0 = 1.0f / l0;
    const float inv1 = 1.0f / l1;
    const size_t r0 = baseRow + qblk * QTILE + wm + lr;
#pragma unroll
    for (int ni = 0; ni < 8; ni++) {
        const int col = colOff + ni * 8 + lc * 2;
        float2 o0, o1;
        o0.x = oacc[ni][0] * inv0; o0.y = oacc[ni][1] * inv0;
        o1.x = oacc[ni][2] * inv1; o1.y = oacc[ni][3] * inv1;
        *reinterpret_cast<float2*>(&g_O[r0 * D_MODEL + col]) = o0;
        *reinterpret_cast<float2*>(&g_O[(r0 + 8) * D_MODEL + col]) = o1;
    }
}

// ---------------------------------------------------------------------------
extern "C" void kernel_launch(void* const* d_in, const int* in_sizes, int n_in,
                              void* d_out, int out_size)
{
    const float* queries = (const float*)d_in[0];
    const float* keys    = (const float*)d_in[1];
    const float* values  = (const float*)d_in[2];
    const float* Wq = (const float*)d_in[3];
    const float* bq = (const float*)d_in[4];
    const float* Wk = (const float*)d_in[5];
    const float* bk = (const float*)d_in[6];
    const float* Wv = (const float*)d_in[7];
    const float* bv = (const float*)d_in[8];
    const float* Wo = (const float*)d_in[9];
    const float* bo = (const float*)d_in[10];
    float* out = (float*)d_out;

    float *Qp, *Kp, *Vp, *Op;
    cudaGetSymbolAddress((void**)&Qp, g_Q);
    cudaGetSymbolAddress((void**)&Kp, g_K);
    cudaGetSymbolAddress((void**)&Vp, g_V);
    cudaGetSymbolAddress((void**)&Op, g_O);

    const dim3 gemmGrid(D_MODEL / BN, MTOT / BM);   // (8, 32)

    gemm_tf32_kernel<<<gemmGrid, 256>>>(queries, Wq, bq, Qp);
    gemm_tf32_kernel<<<gemmGrid, 256>>>(keys,    Wk, bk, Kp);
    gemm_tf32_kernel<<<gemmGrid, 256>>>(values,  Wv, bv, Vp);

    cudaFuncSetAttribute(attn_kernel,
                         cudaFuncAttributeMaxDynamicSharedMemorySize, ATTN_SMEM);
    attn_kernel<<<dim3(SEQ / QTILE, BATCH * HEADS), 256, ATTN_SMEM>>>();

    gemm_tf32_kernel<<<gemmGrid, 256>>>(Op, Wo, bo, out);
}

// round 4
// speedup vs baseline: 2.9070x; 1.1087x over previous
#include <cuda_runtime.h>
#include <math.h>
#include <stdint.h>

// Problem constants
#define D_MODEL 1024
#define SEQ     2048
#define BATCH   2
#define HEADS   16
#define HEAD_DIM 64
#define MTOT (BATCH * SEQ)   // 4096 rows

// Scratch (device globals). g_Q/g_K/g_V hold tf32 bit patterns after the
// projection GEMMs (Q additionally pre-scaled by 1/sqrt(D)). g_O is fp32.
__device__ float g_Q[MTOT * D_MODEL];
__device__ float g_K[MTOT * D_MODEL];
__device__ float g_V[MTOT * D_MODEL];
__device__ float g_O[MTOT * D_MODEL];

__device__ __forceinline__ uint32_t f2tf32(float x) {
    uint32_t u;
    asm("cvt.rna.tf32.f32 %0, %1;" : "=r"(u) : "f"(x));
    return u;
}

__device__ __forceinline__ void mma_tf32(
    float& d0, float& d1, float& d2, float& d3,
    uint32_t a0, uint32_t a1, uint32_t a2, uint32_t a3,
    uint32_t b0, uint32_t b1)
{
    asm volatile(
        "mma.sync.aligned.m16n8k8.row.col.f32.tf32.tf32.f32 "
        "{%0,%1,%2,%3}, {%4,%5,%6,%7}, {%8,%9}, {%0,%1,%2,%3};\n"
        : "+f"(d0), "+f"(d1), "+f"(d2), "+f"(d3)
        : "r"(a0), "r"(a1), "r"(a2), "r"(a3), "r"(b0), "r"(b1));
}

__device__ __forceinline__ void cp16(uint32_t saddr, const float* g) {
    asm volatile("cp.async.cg.shared.global [%0], [%1], 16;\n"
                 :: "r"(saddr), "l"(g));
}
__device__ __forceinline__ void cp_commit() {
    asm volatile("cp.async.commit_group;\n");
}
__device__ __forceinline__ void cp_wait1() {
    asm volatile("cp.async.wait_group 1;\n");
}
__device__ __forceinline__ void cp_wait0() {
    asm volatile("cp.async.wait_group 0;\n");
}

// ---------------------------------------------------------------------------
// tf32 tensor-core GEMM body. CVT=true -> output stored as tf32 bit pattern
// (rounded, post-bias, times outScale). CVT=false -> fp32 output.
// ---------------------------------------------------------------------------
#define BM 128
#define BN 128
#define BK 16
#define SA_STRIDE 20
#define SB_STRIDE 136

template <bool CVT>
__device__ __forceinline__ void gemm_body(
    const float* __restrict__ A, const float* __restrict__ W,
    const float* __restrict__ bias, float* __restrict__ C, float outScale,
    uint32_t (*As)[BM][SA_STRIDE], uint32_t (*Bs)[BK][SB_STRIDE])
{
    const int tid  = threadIdx.x;
    const int warp = tid >> 5;
    const int lane = tid & 31;
    const int wm = (warp & 1) * 64;
    const int wn = (warp >> 1) * 32;
    const int rowBlk = blockIdx.y * BM;
    const int colBlk = blockIdx.x * BN;
    const int lr = lane >> 2;
    const int lc = lane & 3;

    float acc[4][4][4];
#pragma unroll
    for (int mi = 0; mi < 4; mi++)
#pragma unroll
        for (int ni = 0; ni < 4; ni++)
#pragma unroll
            for (int r = 0; r < 4; r++) acc[mi][ni][r] = 0.0f;

    auto load_tile = [&](int t, int buf) {
#pragma unroll
        for (int i = 0; i < 2; i++) {
            const int idx = tid + 256 * i;
            const int r  = idx >> 2;
            const int c4 = (idx & 3) << 2;
            float4 v = *reinterpret_cast<const float4*>(
                &A[(size_t)(rowBlk + r) * D_MODEL + t * BK + c4]);
            uint4 u;
            u.x = f2tf32(v.x); u.y = f2tf32(v.y);
            u.z = f2tf32(v.z); u.w = f2tf32(v.w);
            *reinterpret_cast<uint4*>(&As[buf][r][c4]) = u;
        }
#pragma unroll
        for (int i = 0; i < 2; i++) {
            const int idx = tid + 256 * i;
            const int k  = idx >> 5;
            const int n4 = (idx & 31) << 2;
            float4 v = *reinterpret_cast<const float4*>(
                &W[(size_t)(t * BK + k) * D_MODEL + colBlk + n4]);
            uint4 u;
            u.x = f2tf32(v.x); u.y = f2tf32(v.y);
            u.z = f2tf32(v.z); u.w = f2tf32(v.w);
            *reinterpret_cast<uint4*>(&Bs[buf][k][n4]) = u;
        }
    };

    load_tile(0, 0);
    __syncthreads();

    const int NT = D_MODEL / BK;
    for (int t = 0; t < NT; t++) {
        const int buf = t & 1;
        if (t + 1 < NT) load_tile(t + 1, (t + 1) & 1);

#pragma unroll
        for (int s = 0; s < 2; s++) {
            const int k0 = s * 8;
            uint32_t af[4][4];
#pragma unroll
            for (int mi = 0; mi < 4; mi++) {
                const int m = wm + mi * 16 + lr;
                af[mi][0] = As[buf][m    ][k0 + lc];
                af[mi][1] = As[buf][m + 8][k0 + lc];
                af[mi][2] = As[buf][m    ][k0 + lc + 4];
                af[mi][3] = As[buf][m + 8][k0 + lc + 4];
            }
            uint32_t bf[4][2];
#pragma unroll
            for (int ni = 0; ni < 4; ni++) {
                const int n = wn + ni * 8 + lr;
                bf[ni][0] = Bs[buf][k0 + lc    ][n];
                bf[ni][1] = Bs[buf][k0 + lc + 4][n];
            }
#pragma unroll
            for (int mi = 0; mi < 4; mi++)
#pragma unroll
                for (int ni = 0; ni < 4; ni++)
                    mma_tf32(acc[mi][ni][0], acc[mi][ni][1],
                             acc[mi][ni][2], acc[mi][ni][3],
                             af[mi][0], af[mi][1], af[mi][2], af[mi][3],
                             bf[ni][0], bf[ni][1]);
        }
        __syncthreads();
    }

#pragma unroll
    for (int mi = 0; mi < 4; mi++) {
        const int row0 = rowBlk + wm + mi * 16 + lr;
#pragma unroll
        for (int ni = 0; ni < 4; ni++) {
            const int col = colBlk + wn + ni * 8 + lc * 2;
            const float2 bb = *reinterpret_cast<const float2*>(&bias[col]);
            float v00 = (acc[mi][ni][0] + bb.x) * outScale;
            float v01 = (acc[mi][ni][1] + bb.y) * outScale;
            float v10 = (acc[mi][ni][2] + bb.x) * outScale;
            float v11 = (acc[mi][ni][3] + bb.y) * outScale;
            if (CVT) {
                uint2 u0, u1;
                u0.x = f2tf32(v00); u0.y = f2tf32(v01);
                u1.x = f2tf32(v10); u1.y = f2tf32(v11);
                *reinterpret_cast<uint2*>(&C[(size_t)row0 * D_MODEL + col]) = u0;
                *reinterpret_cast<uint2*>(&C[(size_t)(row0 + 8) * D_MODEL + col]) = u1;
            } else {
                float2 o0, o1;
                o0.x = v00; o0.y = v01;
                o1.x = v10; o1.y = v11;
                *reinterpret_cast<float2*>(&C[(size_t)row0 * D_MODEL + col]) = o0;
                *reinterpret_cast<float2*>(&C[(size_t)(row0 + 8) * D_MODEL + col]) = o1;
            }
        }
    }
}

// Merged Q/K/V projection: blockIdx.z selects which projection.
__global__ __launch_bounds__(256) void qkv_gemm_kernel(
    const float* __restrict__ q,  const float* __restrict__ k,
    const float* __restrict__ v,
    const float* __restrict__ Wq, const float* __restrict__ Wk,
    const float* __restrict__ Wv,
    const float* __restrict__ bq, const float* __restrict__ bk,
    const float* __restrict__ bv,
    float* __restrict__ Qo, float* __restrict__ Ko, float* __restrict__ Vo)
{
    __shared__ uint32_t As[2][BM][SA_STRIDE];
    __shared__ uint32_t Bs[2][BK][SB_STRIDE];
    const int z = blockIdx.z;
    const float* A  = (z == 0) ? q  : (z == 1) ? k  : v;
    const float* W  = (z == 0) ? Wq : (z == 1) ? Wk : Wv;
    const float* bb = (z == 0) ? bq : (z == 1) ? bk : bv;
    float*       C  = (z == 0) ? Qo : (z == 1) ? Ko : Vo;
    const float  sc = (z == 0) ? 0.03125f : 1.0f;   // 1/sqrt(1024) folded into Q
    gemm_body<true>(A, W, bb, C, sc, As, Bs);
}

__global__ __launch_bounds__(256) void gemm_o_kernel(
    const float* __restrict__ A, const float* __restrict__ W,
    const float* __restrict__ bias, float* __restrict__ C)
{
    __shared__ uint32_t As[2][BM][SA_STRIDE];
    __shared__ uint32_t Bs[2][BK][SB_STRIDE];
    gemm_body<false>(A, W, bias, C, 1.0f, As, Bs);
}

// ---------------------------------------------------------------------------
// tf32 flash attention with cp.async double-buffered K/V (already tf32 in
// GMEM; Q already tf32 + pre-scaled). Block = 128 q-rows of one (b,h).
// ---------------------------------------------------------------------------
#define QTILE 128
#define KCH 64
#define KST 68            // K / P smem stride (== 4 mod 32, conflict-free)
#define VST 72            // V smem stride (== 8 mod 32, conflict-free)
#define ASM_K (64 * KST)
#define ASM_V (64 * VST)
#define KOFF_V (2 * ASM_K)
#define POFF  (2 * ASM_K + 2 * ASM_V)
#define ASM_P (QTILE * KST)
#define ATTN_SMEM ((POFF + ASM_P) * 4)   // 106496 bytes
#define NTC (SEQ / KCH)                  // 32

__global__ __launch_bounds__(256) void attn_kernel()
{
    extern __shared__ uint32_t smu[];
    const uint32_t su = (uint32_t)__cvta_generic_to_shared(smu);
    uint32_t* Psm = smu + POFF;

    const int tid  = threadIdx.x;
    const int warp = tid >> 5;
    const int lane = tid & 31;
    const int lr = lane >> 2;
    const int lc = lane & 3;
    const int wm = warp * 16;

    const int qblk = blockIdx.x;
    const int bh   = blockIdx.y;
    const int b = bh >> 4;
    const int h = bh & 15;
    const size_t baseRow = (size_t)b * SEQ;
    const int colOff = h * HEAD_DIM;

    auto issue_chunk = [&](int kt, int buf) {
#pragma unroll
        for (int i = 0; i < 4; i++) {
            const int idx = tid + 256 * i;
            const int r  = idx >> 4;
            const int d4 = (idx & 15) << 2;
            const size_t g = (baseRow + (size_t)kt * KCH + r) * D_MODEL + colOff + d4;
            cp16(su + (uint32_t)(buf * ASM_K + r * KST + d4) * 4, &g_K[g]);
            cp16(su + (uint32_t)(KOFF_V + buf * ASM_V + r * VST + d4) * 4, &g_V[g]);
        }
        cp_commit();
    };

    // start loading chunk 0 immediately
    issue_chunk(0, 0);

    // stage Q tile (raw tf32 copy; already scaled) into Psm
#pragma unroll
    for (int i = 0; i < 8; i++) {
        const int idx = tid + 256 * i;
        const int r  = idx >> 4;
        const int d4 = (idx & 15) << 2;
        *reinterpret_cast<uint4*>(&Psm[r * KST + d4]) =
            *reinterpret_cast<const uint4*>(
                &g_Q[(baseRow + qblk * QTILE + r) * D_MODEL + colOff + d4]);
    }
    __syncthreads();

    uint32_t qf[8][4];
#pragma unroll
    for (int ks = 0; ks < 8; ks++) {
        const int k0 = ks * 8;
        qf[ks][0] = Psm[(wm + lr    ) * KST + k0 + lc    ];
        qf[ks][1] = Psm[(wm + lr + 8) * KST + k0 + lc    ];
        qf[ks][2] = Psm[(wm + lr    ) * KST + k0 + lc + 4];
        qf[ks][3] = Psm[(wm + lr + 8) * KST + k0 + lc + 4];
    }
    // qf reads and later P writes touch only this warp's rows -> no cross-warp
    // hazard; the syncthreads above ordered staging vs reads.

    float oacc[8][4];
#pragma unroll
    for (int ni = 0; ni < 8; ni++)
#pragma unroll
        for (int r = 0; r < 4; r++) oacc[ni][r] = 0.0f;
    float m0 = -INFINITY, m1 = -INFINITY, l0 = 0.0f, l1 = 0.0f;

    for (int kt = 0; kt < NTC; kt++) {
        const int buf = kt & 1;
        if (kt + 1 < NTC) {
            issue_chunk(kt + 1, buf ^ 1);   // prefetch next chunk
            cp_wait1();                     // current chunk's group complete
        } else {
            cp_wait0();
        }
        __syncthreads();

        const uint32_t* Ksm = smu + buf * ASM_K;
        const uint32_t* Vsm = smu + KOFF_V + buf * ASM_V;

        // ---- S = Q @ K^T ----
        float sacc[8][4];
#pragma unroll
        for (int ni = 0; ni < 8; ni++)
#pragma unroll
            for (int r = 0; r < 4; r++) sacc[ni][r] = 0.0f;
#pragma unroll
        for (int ks = 0; ks < 8; ks++) {
            const int k0 = ks * 8;
#pragma unroll
            for (int ni = 0; ni < 8; ni++) {
                const uint32_t b0 = Ksm[(ni * 8 + lr) * KST + k0 + lc    ];
                const uint32_t b1 = Ksm[(ni * 8 + lr) * KST + k0 + lc + 4];
                mma_tf32(sacc[ni][0], sacc[ni][1], sacc[ni][2], sacc[ni][3],
                         qf[ks][0], qf[ks][1], qf[ks][2], qf[ks][3], b0, b1);
            }
        }

        // ---- online softmax (warp-local, 4 lanes/row) ----
        float lm0 = -INFINITY, lm1 = -INFINITY;
#pragma unroll
        for (int ni = 0; ni < 8; ni++) {
            lm0 = fmaxf(lm0, fmaxf(sacc[ni][0], sacc[ni][1]));
            lm1 = fmaxf(lm1, fmaxf(sacc[ni][2], sacc[ni][3]));
        }
        lm0 = fmaxf(lm0, __shfl_xor_sync(0xffffffffu, lm0, 1));
        lm0 = fmaxf(lm0, __shfl_xor_sync(0xffffffffu, lm0, 2));
        lm1 = fmaxf(lm1, __shfl_xor_sync(0xffffffffu, lm1, 1));
        lm1 = fmaxf(lm1, __shfl_xor_sync(0xffffffffu, lm1, 2));
        const float mn0 = fmaxf(m0, lm0);
        const float mn1 = fmaxf(m1, lm1);
        const float a0 = __expf(m0 - mn0);
        const float a1 = __expf(m1 - mn1);
        m0 = mn0; m1 = mn1;
        float rs0 = 0.0f, rs1 = 0.0f;
#pragma unroll
        for (int ni = 0; ni < 8; ni++) {
            sacc[ni][0] = __expf(sacc[ni][0] - mn0);
            sacc[ni][1] = __expf(sacc[ni][1] - mn0);
            sacc[ni][2] = __expf(sacc[ni][2] - mn1);
            sacc[ni][3] = __expf(sacc[ni][3] - mn1);
            rs0 += sacc[ni][0] + sacc[ni][1];
            rs1 += sacc[ni][2] + sacc[ni][3];
        }
        rs0 += __shfl_xor_sync(0xffffffffu, rs0, 1);
        rs0 += __shfl_xor_sync(0xffffffffu, rs0, 2);
        rs1 += __shfl_xor_sync(0xffffffffu, rs1, 1);
        rs1 += __shfl_xor_sync(0xffffffffu, rs1, 2);
        l0 = l0 * a0 + rs0;
        l1 = l1 * a1 + rs1;
#pragma unroll
        for (int ni = 0; ni < 8; ni++) {
            oacc[ni][0] *= a0; oacc[ni][1] *= a0;
            oacc[ni][2] *= a1; oacc[ni][3] *= a1;
        }

        // ---- write P (tf32) to smem (warp-private rows) ----
#pragma unroll
        for (int ni = 0; ni < 8; ni++) {
            const int col = ni * 8 + lc * 2;
            uint2 p0, p1;
            p0.x = f2tf32(sacc[ni][0]); p0.y = f2tf32(sacc[ni][1]);
            p1.x = f2tf32(sacc[ni][2]); p1.y = f2tf32(sacc[ni][3]);
            *reinterpret_cast<uint2*>(&Psm[(wm + lr    ) * KST + col]) = p0;
            *reinterpret_cast<uint2*>(&Psm[(wm + lr + 8) * KST + col]) = p1;
        }
        __syncwarp();

        // ---- O += P @ V ----
#pragma unroll
        for (int ks = 0; ks < 8; ks++) {
            const int k0 = ks * 8;
            uint32_t af0 = Psm[(wm + lr    ) * KST + k0 + lc    ];
            uint32_t af1 = Psm[(wm + lr + 8) * KST + k0 + lc    ];
            uint32_t af2 = Psm[(wm + lr    ) * KST + k0 + lc + 4];
            uint32_t af3 = Psm[(wm + lr + 8) * KST + k0 + lc + 4];
#pragma unroll
            for (int ni = 0; ni < 8; ni++) {
                const uint32_t b0 = Vsm[(k0 + lc    ) * VST + ni * 8 + lr];
                const uint32_t b1 = Vsm[(k0 + lc + 4) * VST + ni * 8 + lr];
                mma_tf32(oacc[ni][0], oacc[ni][1], oacc[ni][2], oacc[ni][3],
                         af0, af1, af2, af3, b0, b1);
            }
        }
        __syncthreads();   // all warps done with buf before it is re-filled
    }

    // ---- normalize and store (fp32) ----
    const float inv0 = 1.0f / l0;
    const float inv1 = 1.0f / l1;
    const size_t r0 = baseRow + qblk * QTILE + wm + lr;
#pragma unroll
    for (int ni = 0; ni < 8; ni++) {
        const int col = colOff + ni * 8 + lc * 2;
        float2 o0, o1;
        o0.x = oacc[ni][0] * inv0; o0.y = oacc[ni][1] * inv0;
        o1.x = oacc[ni][2] * inv1; o1.y = oacc[ni][3] * inv1;
        *reinterpret_cast<float2*>(&g_O[r0 * D_MODEL + col]) = o0;
        *reinterpret_cast<float2*>(&g_O[(r0 + 8) * D_MODEL + col]) = o1;
    }
}

// ---------------------------------------------------------------------------
extern "C" void kernel_launch(void* const* d_in, const int* in_sizes, int n_in,
                              void* d_out, int out_size)
{
    const float* queries = (const float*)d_in[0];
    const float* keys    = (const float*)d_in[1];
    const float* values  = (const float*)d_in[2];
    const float* Wq = (const float*)d_in[3];
    const float* bq = (const float*)d_in[4];
    const float* Wk = (const float*)d_in[5];
    const float* bk = (const float*)d_in[6];
    const float* Wv = (const float*)d_in[7];
    const float* bv = (const float*)d_in[8];
    const float* Wo = (const float*)d_in[9];
    const float* bo = (const float*)d_in[10];
    float* out = (float*)d_out;

    float *Qp, *Kp, *Vp, *Op;
    cudaGetSymbolAddress((void**)&Qp, g_Q);
    cudaGetSymbolAddress((void**)&Kp, g_K);
    cudaGetSymbolAddress((void**)&Vp, g_V);
    cudaGetSymbolAddress((void**)&Op, g_O);

    qkv_gemm_kernel<<<dim3(D_MODEL / BN, MTOT / BM, 3), 256>>>(
        queries, keys, values, Wq, Wk, Wv, bq, bk, bv, Qp, Kp, Vp);

    cudaFuncSetAttribute(attn_kernel,
                         cudaFuncAttributeMaxDynamicSharedMemorySize, ATTN_SMEM);
    attn_kernel<<<dim3(SEQ / QTILE, BATCH * HEADS), 256, ATTN_SMEM>>>();

    gemm_o_kernel<<<dim3(D_MODEL / BN, MTOT / BM), 256>>>(Op, Wo, bo, out);
}

// round 5
// speedup vs baseline: 3.4624x; 1.1910x over previous
#include <cuda_runtime.h>
#include <math.h>
#include <stdint.h>

// Problem constants
#define D_MODEL 1024
#define SEQ     2048
#define BATCH   2
#define HEADS   16
#define HEAD_DIM 64
#define MTOT (BATCH * SEQ)   // 4096 rows

// Scratch (device globals; no allocation allowed).
// tf32 bit patterns throughout the pipeline interior:
__device__ float g_Q[MTOT * D_MODEL];    // tf32, pre-scaled by 1/sqrt(D)
__device__ float g_K[MTOT * D_MODEL];    // tf32
__device__ float g_V[MTOT * D_MODEL];    // tf32
__device__ float g_O[MTOT * D_MODEL];    // tf32 (attn output)
__device__ float g_Xq[MTOT * D_MODEL];   // tf32 copy of queries
__device__ float g_Xk[MTOT * D_MODEL];   // tf32 copy of keys
__device__ float g_Xv[MTOT * D_MODEL];   // tf32 copy of values
__device__ float g_Wqt[D_MODEL * D_MODEL];
__device__ float g_Wkt[D_MODEL * D_MODEL];
__device__ float g_Wvt[D_MODEL * D_MODEL];
__device__ float g_Wot[D_MODEL * D_MODEL];

__device__ __forceinline__ uint32_t f2tf32(float x) {
    uint32_t u;
    asm("cvt.rna.tf32.f32 %0, %1;" : "=r"(u) : "f"(x));
    return u;
}

__device__ __forceinline__ void mma_tf32(
    float& d0, float& d1, float& d2, float& d3,
    uint32_t a0, uint32_t a1, uint32_t a2, uint32_t a3,
    uint32_t b0, uint32_t b1)
{
    asm volatile(
        "mma.sync.aligned.m16n8k8.row.col.f32.tf32.tf32.f32 "
        "{%0,%1,%2,%3}, {%4,%5,%6,%7}, {%8,%9}, {%0,%1,%2,%3};\n"
        : "+f"(d0), "+f"(d1), "+f"(d2), "+f"(d3)
        : "r"(a0), "r"(a1), "r"(a2), "r"(a3), "r"(b0), "r"(b1));
}

__device__ __forceinline__ void cp16(uint32_t saddr, const float* g) {
    asm volatile("cp.async.cg.shared.global [%0], [%1], 16;\n"
                 :: "r"(saddr), "l"(g));
}
__device__ __forceinline__ void cp_commit() {
    asm volatile("cp.async.commit_group;\n");
}
template <int N>
__device__ __forceinline__ void cp_wait() {
    asm volatile("cp.async.wait_group %0;\n" :: "n"(N));
}

// ---------------------------------------------------------------------------
// Prep: round-to-nearest tf32 conversion of inputs + weights (bit-identical
// to the cvt the old GEMM applied at load time).
// ---------------------------------------------------------------------------
__global__ __launch_bounds__(256) void prep_kernel(
    const float* __restrict__ q, const float* __restrict__ k,
    const float* __restrict__ v,
    const float* __restrict__ Wq, const float* __restrict__ Wk,
    const float* __restrict__ Wv, const float* __restrict__ Wo)
{
    const int z = blockIdx.y;
    const float* src;
    float* dst;
    int n4;   // number of float4 elements
    switch (z) {
        case 0: src = q;  dst = g_Xq;  n4 = MTOT * D_MODEL / 4; break;
        case 1: src = k;  dst = g_Xk;  n4 = MTOT * D_MODEL / 4; break;
        case 2: src = v;  dst = g_Xv;  n4 = MTOT * D_MODEL / 4; break;
        case 3: src = Wq; dst = g_Wqt; n4 = D_MODEL * D_MODEL / 4; break;
        case 4: src = Wk; dst = g_Wkt; n4 = D_MODEL * D_MODEL / 4; break;
        case 5: src = Wv; dst = g_Wvt; n4 = D_MODEL * D_MODEL / 4; break;
        default:src = Wo; dst = g_Wot; n4 = D_MODEL * D_MODEL / 4; break;
    }
    const int i = blockIdx.x * 256 + threadIdx.x;
    if (i < n4) {
        float4 vld = reinterpret_cast<const float4*>(src)[i];
        uint4 u;
        u.x = f2tf32(vld.x); u.y = f2tf32(vld.y);
        u.z = f2tf32(vld.z); u.w = f2tf32(vld.w);
        reinterpret_cast<uint4*>(dst)[i] = u;
    }
}

// ---------------------------------------------------------------------------
// tf32 GEMM, fully cp.async: A/W already tf32 bits in GMEM. 128x128 tile,
// BK=16, 4-stage pipeline, 256 threads, 8 warps (64x32 warp tile).
// A smem m-major stride 20 (rows = 80B, 16B-aligned); B k-major stride 136
// (rows = 544B). Conflict-free frag gathers proven in R2-R4.
// CVT: output stored as tf32 bits (post-bias, *outScale); else fp32.
// ---------------------------------------------------------------------------
#define BM 128
#define BN 128
#define BK 16
#define SA_ST 20
#define SB_ST 136
#define STAGES 4
#define AS_WORDS (BM * SA_ST)            // 2560
#define BS_WORDS (BK * SB_ST)            // 2176
#define AS_TOT (STAGES * AS_WORDS)       // 10240
#define GEMM_SMEM ((AS_TOT + STAGES * BS_WORDS) * 4)   // 75776 bytes

template <bool CVT>
__device__ __forceinline__ void gemm_body(
    const float* __restrict__ A, const float* __restrict__ W,
    const float* __restrict__ bias, float* __restrict__ C, float outScale)
{
    extern __shared__ uint32_t gsm[];
    const uint32_t su = (uint32_t)__cvta_generic_to_shared(gsm);

    const int tid  = threadIdx.x;
    const int warp = tid >> 5;
    const int lane = tid & 31;
    const int wm = (warp & 1) * 64;
    const int wn = (warp >> 1) * 32;
    const int rowBlk = blockIdx.y * BM;
    const int colBlk = blockIdx.x * BN;
    const int lr = lane >> 2;
    const int lc = lane & 3;

    // per-thread copy coords (2 x 16B for A, 2 x 16B for B per tile)
    const int ar0 = tid >> 2;                 // A rows for idx=tid, tid+256
    const int ac0 = (tid & 3) << 2;
    const int bk0 = tid >> 5;                 // B k for idx=tid, tid+256
    const int bn0 = (tid & 31) << 2;

    auto issue = [&](int t, int s) {
        const uint32_t abase = su + (uint32_t)(s * AS_WORDS) * 4;
        const uint32_t bbase = su + (uint32_t)(AS_TOT + s * BS_WORDS) * 4;
        cp16(abase + (uint32_t)(ar0 * SA_ST + ac0) * 4,
             &A[(size_t)(rowBlk + ar0) * D_MODEL + t * BK + ac0]);
        cp16(abase + (uint32_t)((ar0 + 64) * SA_ST + ac0) * 4,
             &A[(size_t)(rowBlk + ar0 + 64) * D_MODEL + t * BK + ac0]);
        cp16(bbase + (uint32_t)(bk0 * SB_ST + bn0) * 4,
             &W[(size_t)(t * BK + bk0) * D_MODEL + colBlk + bn0]);
        cp16(bbase + (uint32_t)((bk0 + 8) * SB_ST + bn0) * 4,
             &W[(size_t)(t * BK + bk0 + 8) * D_MODEL + colBlk + bn0]);
        cp_commit();
    };

    float acc[4][4][4];
#pragma unroll
    for (int mi = 0; mi < 4; mi++)
#pragma unroll
        for (int ni = 0; ni < 4; ni++)
#pragma unroll
            for (int r = 0; r < 4; r++) acc[mi][ni][r] = 0.0f;

    // prologue: fill stages 0..2
    issue(0, 0);
    issue(1, 1);
    issue(2, 2);

    const int NT = D_MODEL / BK;   // 64
    for (int t = 0; t < NT; t++) {
        cp_wait<2>();          // group t complete (≤2 pending of t+1,t+2)
        __syncthreads();       // all warps past iter t-1 reads; copies visible
        if (t + 3 < NT) issue(t + 3, (t + 3) & (STAGES - 1));

        const int s = t & (STAGES - 1);
        const uint32_t* As = gsm + s * AS_WORDS;
        const uint32_t* Bs = gsm + AS_TOT + s * BS_WORDS;

#pragma unroll
        for (int ss = 0; ss < 2; ss++) {
            const int k0 = ss * 8;
            uint32_t af[4][4];
#pragma unroll
            for (int mi = 0; mi < 4; mi++) {
                const int m = wm + mi * 16 + lr;
                af[mi][0] = As[m * SA_ST + k0 + lc];
                af[mi][1] = As[(m + 8) * SA_ST + k0 + lc];
                af[mi][2] = As[m * SA_ST + k0 + lc + 4];
                af[mi][3] = As[(m + 8) * SA_ST + k0 + lc + 4];
            }
            uint32_t bf[4][2];
#pragma unroll
            for (int ni = 0; ni < 4; ni++) {
                const int n = wn + ni * 8 + lr;
                bf[ni][0] = Bs[(k0 + lc) * SB_ST + n];
                bf[ni][1] = Bs[(k0 + lc + 4) * SB_ST + n];
            }
#pragma unroll
            for (int mi = 0; mi < 4; mi++)
#pragma unroll
                for (int ni = 0; ni < 4; ni++)
                    mma_tf32(acc[mi][ni][0], acc[mi][ni][1],
                             acc[mi][ni][2], acc[mi][ni][3],
                             af[mi][0], af[mi][1], af[mi][2], af[mi][3],
                             bf[ni][0], bf[ni][1]);
        }
    }

#pragma unroll
    for (int mi = 0; mi < 4; mi++) {
        const int row0 = rowBlk + wm + mi * 16 + lr;
#pragma unroll
        for (int ni = 0; ni < 4; ni++) {
            const int col = colBlk + wn + ni * 8 + lc * 2;
            const float2 bb = *reinterpret_cast<const float2*>(&bias[col]);
            float v00 = (acc[mi][ni][0] + bb.x) * outScale;
            float v01 = (acc[mi][ni][1] + bb.y) * outScale;
            float v10 = (acc[mi][ni][2] + bb.x) * outScale;
            float v11 = (acc[mi][ni][3] + bb.y) * outScale;
            if (CVT) {
                uint2 u0, u1;
                u0.x = f2tf32(v00); u0.y = f2tf32(v01);
                u1.x = f2tf32(v10); u1.y = f2tf32(v11);
                *reinterpret_cast<uint2*>(&C[(size_t)row0 * D_MODEL + col]) = u0;
                *reinterpret_cast<uint2*>(&C[(size_t)(row0 + 8) * D_MODEL + col]) = u1;
            } else {
                float2 o0, o1;
                o0.x = v00; o0.y = v01;
                o1.x = v10; o1.y = v11;
                *reinterpret_cast<float2*>(&C[(size_t)row0 * D_MODEL + col]) = o0;
                *reinterpret_cast<float2*>(&C[(size_t)(row0 + 8) * D_MODEL + col]) = o1;
            }
        }
    }
}

__global__ __launch_bounds__(256, 2) void qkv_gemm_kernel()
{
    const int z = blockIdx.z;
    const float* A = (z == 0) ? g_Xq : (z == 1) ? g_Xk : g_Xv;
    const float* W = (z == 0) ? g_Wqt : (z == 1) ? g_Wkt : g_Wvt;
    float*       C = (z == 0) ? g_Q : (z == 1) ? g_K : g_V;
    const float sc = (z == 0) ? 0.03125f : 1.0f;   // fold 1/sqrt(1024) into Q
    gemm_body<true>(A, W, nullptr, C, sc);
}

// biases for qkv are zero in this problem? NO — biases are inputs; must use them.
// (bq/bk/bv are zeros per setup, but contract says use the tensors.)
__global__ __launch_bounds__(256, 2) void qkv_gemm_kernel_b(
    const float* __restrict__ bq, const float* __restrict__ bk,
    const float* __restrict__ bv)
{
    const int z = blockIdx.z;
    const float* A = (z == 0) ? g_Xq : (z == 1) ? g_Xk : g_Xv;
    const float* W = (z == 0) ? g_Wqt : (z == 1) ? g_Wkt : g_Wvt;
    const float* b = (z == 0) ? bq : (z == 1) ? bk : bv;
    float*       C = (z == 0) ? g_Q : (z == 1) ? g_K : g_V;
    const float sc = (z == 0) ? 0.03125f : 1.0f;
    gemm_body<true>(A, W, b, C, sc);
}

__global__ __launch_bounds__(256, 2) void gemm_o_kernel(
    const float* __restrict__ bias, float* __restrict__ C)
{
    gemm_body<false>(g_O, g_Wot, bias, C, 1.0f);
}

// ---------------------------------------------------------------------------
// tf32 flash attention (R4 version; only change: O stored as tf32 bits).
// ---------------------------------------------------------------------------
#define QTILE 128
#define KCH 64
#define KST 68
#define VST 72
#define ASM_K (64 * KST)
#define ASM_V (64 * VST)
#define KOFF_V (2 * ASM_K)
#define POFF  (2 * ASM_K + 2 * ASM_V)
#define ASM_P (QTILE * KST)
#define ATTN_SMEM ((POFF + ASM_P) * 4)   // 106496 bytes
#define NTC (SEQ / KCH)                  // 32

__global__ __launch_bounds__(256) void attn_kernel()
{
    extern __shared__ uint32_t smu[];
    const uint32_t su = (uint32_t)__cvta_generic_to_shared(smu);
    uint32_t* Psm = smu + POFF;

    const int tid  = threadIdx.x;
    const int warp = tid >> 5;
    const int lane = tid & 31;
    const int lr = lane >> 2;
    const int lc = lane & 3;
    const int wm = warp * 16;

    const int qblk = blockIdx.x;
    const int bh   = blockIdx.y;
    const int b = bh >> 4;
    const int h = bh & 15;
    const size_t baseRow = (size_t)b * SEQ;
    const int colOff = h * HEAD_DIM;

    auto issue_chunk = [&](int kt, int buf) {
#pragma unroll
        for (int i = 0; i < 4; i++) {
            const int idx = tid + 256 * i;
            const int r  = idx >> 4;
            const int d4 = (idx & 15) << 2;
            const size_t g = (baseRow + (size_t)kt * KCH + r) * D_MODEL + colOff + d4;
            cp16(su + (uint32_t)(buf * ASM_K + r * KST + d4) * 4, &g_K[g]);
            cp16(su + (uint32_t)(KOFF_V + buf * ASM_V + r * VST + d4) * 4, &g_V[g]);
        }
        cp_commit();
    };

    issue_chunk(0, 0);

#pragma unroll
    for (int i = 0; i < 8; i++) {
        const int idx = tid + 256 * i;
        const int r  = idx >> 4;
        const int d4 = (idx & 15) << 2;
        *reinterpret_cast<uint4*>(&Psm[r * KST + d4]) =
            *reinterpret_cast<const uint4*>(
                &g_Q[(baseRow + qblk * QTILE + r) * D_MODEL + colOff + d4]);
    }
    __syncthreads();

    uint32_t qf[8][4];
#pragma unroll
    for (int ks = 0; ks < 8; ks++) {
        const int k0 = ks * 8;
        qf[ks][0] = Psm[(wm + lr    ) * KST + k0 + lc    ];
        qf[ks][1] = Psm[(wm + lr + 8) * KST + k0 + lc    ];
        qf[ks][2] = Psm[(wm + lr    ) * KST + k0 + lc + 4];
        qf[ks][3] = Psm[(wm + lr + 8) * KST + k0 + lc + 4];
    }

    float oacc[8][4];
#pragma unroll
    for (int ni = 0; ni < 8; ni++)
#pragma unroll
        for (int r = 0; r < 4; r++) oacc[ni][r] = 0.0f;
    float m0 = -INFINITY, m1 = -INFINITY, l0 = 0.0f, l1 = 0.0f;

    for (int kt = 0; kt < NTC; kt++) {
        const int buf = kt & 1;
        if (kt + 1 < NTC) {
            issue_chunk(kt + 1, buf ^ 1);
            cp_wait<1>();
        } else {
            cp_wait<0>();
        }
        __syncthreads();

        const uint32_t* Ksm = smu + buf * ASM_K;
        const uint32_t* Vsm = smu + KOFF_V + buf * ASM_V;

        float sacc[8][4];
#pragma unroll
        for (int ni = 0; ni < 8; ni++)
#pragma unroll
            for (int r = 0; r < 4; r++) sacc[ni][r] = 0.0f;
#pragma unroll
        for (int ks = 0; ks < 8; ks++) {
            const int k0 = ks * 8;
#pragma unroll
            for (int ni = 0; ni < 8; ni++) {
                const uint32_t b0 = Ksm[(ni * 8 + lr) * KST + k0 + lc    ];
                const uint32_t b1 = Ksm[(ni * 8 + lr) * KST + k0 + lc + 4];
                mma_tf32(sacc[ni][0], sacc[ni][1], sacc[ni][2], sacc[ni][3],
                         qf[ks][0], qf[ks][1], qf[ks][2], qf[ks][3], b0, b1);
            }
        }

        float lm0 = -INFINITY, lm1 = -INFINITY;
#pragma unroll
        for (int ni = 0; ni < 8; ni++) {
            lm0 = fmaxf(lm0, fmaxf(sacc[ni][0], sacc[ni][1]));
            lm1 = fmaxf(lm1, fmaxf(sacc[ni][2], sacc[ni][3]));
        }
        lm0 = fmaxf(lm0, __shfl_xor_sync(0xffffffffu, lm0, 1));
        lm0 = fmaxf(lm0, __shfl_xor_sync(0xffffffffu, lm0, 2));
        lm1 = fmaxf(lm1, __shfl_xor_sync(0xffffffffu, lm1, 1));
        lm1 = fmaxf(lm1, __shfl_xor_sync(0xffffffffu, lm1, 2));
        const float mn0 = fmaxf(m0, lm0);
        const float mn1 = fmaxf(m1, lm1);
        const float a0 = __expf(m0 - mn0);
        const float a1 = __expf(m1 - mn1);
        m0 = mn0; m1 = mn1;
        float rs0 = 0.0f, rs1 = 0.0f;
#pragma unroll
        for (int ni = 0; ni < 8; ni++) {
            sacc[ni][0] = __expf(sacc[ni][0] - mn0);
            sacc[ni][1] = __expf(sacc[ni][1] - mn0);
            sacc[ni][2] = __expf(sacc[ni][2] - mn1);
            sacc[ni][3] = __expf(sacc[ni][3] - mn1);
            rs0 += sacc[ni][0] + sacc[ni][1];
            rs1 += sacc[ni][2] + sacc[ni][3];
        }
        rs0 += __shfl_xor_sync(0xffffffffu, rs0, 1);
        rs0 += __shfl_xor_sync(0xffffffffu, rs0, 2);
        rs1 += __shfl_xor_sync(0xffffffffu, rs1, 1);
        rs1 += __shfl_xor_sync(0xffffffffu, rs1, 2);
        l0 = l0 * a0 + rs0;
        l1 = l1 * a1 + rs1;
#pragma unroll
        for (int ni = 0; ni < 8; ni++) {
            oacc[ni][0] *= a0; oacc[ni][1] *= a0;
            oacc[ni][2] *= a1; oacc[ni][3] *= a1;
        }

#pragma unroll
        for (int ni = 0; ni < 8; ni++) {
            const int col = ni * 8 + lc * 2;
            uint2 p0, p1;
            p0.x = f2tf32(sacc[ni][0]); p0.y = f2tf32(sacc[ni][1]);
            p1.x = f2tf32(sacc[ni][2]); p1.y = f2tf32(sacc[ni][3]);
            *reinterpret_cast<uint2*>(&Psm[(wm + lr    ) * KST + col]) = p0;
            *reinterpret_cast<uint2*>(&Psm[(wm + lr + 8) * KST + col]) = p1;
        }
        __syncwarp();

#pragma unroll
        for (int ks = 0; ks < 8; ks++) {
            const int k0 = ks * 8;
            uint32_t af0 = Psm[(wm + lr    ) * KST + k0 + lc    ];
            uint32_t af1 = Psm[(wm + lr + 8) * KST + k0 + lc    ];
            uint32_t af2 = Psm[(wm + lr    ) * KST + k0 + lc + 4];
            uint32_t af3 = Psm[(wm + lr + 8) * KST + k0 + lc + 4];
#pragma unroll
            for (int ni = 0; ni < 8; ni++) {
                const uint32_t b0 = Vsm[(k0 + lc    ) * VST + ni * 8 + lr];
                const uint32_t b1 = Vsm[(k0 + lc + 4) * VST + ni * 8 + lr];
                mma_tf32(oacc[ni][0], oacc[ni][1], oacc[ni][2], oacc[ni][3],
                         af0, af1, af2, af3, b0, b1);
            }
        }
        __syncthreads();
    }

    // normalize, convert to tf32 bits, store (O-GEMM consumes raw words;
    // identical rounding to the load-time cvt it used to perform)
    const float inv0 = 1.0f / l0;
    const float inv1 = 1.0f / l1;
    const size_t r0 = baseRow + qblk * QTILE + wm + lr;
    uint32_t* Og = reinterpret_cast<uint32_t*>(g_O);
#pragma unroll
    for (int ni = 0; ni < 8; ni++) {
        const int col = colOff + ni * 8 + lc * 2;
        uint2 o0, o1;
        o0.x = f2tf32(oacc[ni][0] * inv0); o0.y = f2tf32(oacc[ni][1] * inv0);
        o1.x = f2tf32(oacc[ni][2] * inv1); o1.y = f2tf32(oacc[ni][3] * inv1);
        *reinterpret_cast<uint2*>(&Og[r0 * D_MODEL + col]) = o0;
        *reinterpret_cast<uint2*>(&Og[(r0 + 8) * D_MODEL + col]) = o1;
    }
}

// ---------------------------------------------------------------------------
extern "C" void kernel_launch(void* const* d_in, const int* in_sizes, int n_in,
                              void* d_out, int out_size)
{
    const float* queries = (const float*)d_in[0];
    const float* keys    = (const float*)d_in[1];
    const float* values  = (const float*)d_in[2];
    const float* Wq = (const float*)d_in[3];
    const float* bq = (const float*)d_in[4];
    const float* Wk = (const float*)d_in[5];
    const float* bk = (const float*)d_in[6];
    const float* Wv = (const float*)d_in[7];
    const float* bv = (const float*)d_in[8];
    const float* Wo = (const float*)d_in[9];
    const float* bo = (const float*)d_in[10];
    float* out = (float*)d_out;

    // prep: tf32-convert inputs + weights
    prep_kernel<<<dim3(MTOT * D_MODEL / 4 / 256, 7), 256>>>(
        queries, keys, values, Wq, Wk, Wv, Wo);

    cudaFuncSetAttribute(qkv_gemm_kernel_b,
                         cudaFuncAttributeMaxDynamicSharedMemorySize, GEMM_SMEM);
    cudaFuncSetAttribute(gemm_o_kernel,
                         cudaFuncAttributeMaxDynamicSharedMemorySize, GEMM_SMEM);
    cudaFuncSetAttribute(attn_kernel,
                         cudaFuncAttributeMaxDynamicSharedMemorySize, ATTN_SMEM);

    qkv_gemm_kernel_b<<<dim3(D_MODEL / BN, MTOT / BM, 3), 256, GEMM_SMEM>>>(
        bq, bk, bv);

    attn_kernel<<<dim3(SEQ / QTILE, BATCH * HEADS), 256, ATTN_SMEM>>>();

    gemm_o_kernel<<<dim3(D_MODEL / BN, MTOT / BM), 256, GEMM_SMEM>>>(bo, out);
}